// round 12
// baseline (speedup 1.0000x reference)
#include <cuda_runtime.h>
#include <cstdint>

#define NBR   19
#define DIMF  768
#define DD    384
#define BSZ   4096
#define XROW  (NBR * DIMF)   // 14592
#define GW    (DIMF + DD)    // 1152

// ---------------- scratch (device globals) ----------------
__device__ float g_fea_u[(size_t)BSZ * DIMF];
__device__ float g_h1[(size_t)BSZ * DD];
__device__ float g_fea_z[(size_t)BSZ * DD];
__device__ float g_att[(size_t)NBR * BSZ * DIMF];    // fea_z @ Wc^T + bc
__device__ float g_att2[(size_t)NBR * BSZ * DIMF];   // g @ gfcsB^T
__device__ float g_fea_v[(size_t)BSZ * DIMF];
__device__ float g_hA[(size_t)BSZ * 128];
__device__ float g_hB[(size_t)BSZ * 32];
__device__ float g_Wc[(size_t)NBR * DIMF * DD];
__device__ float g_fcsT[(size_t)NBR * DD * DD];
__device__ float g_bc[(size_t)NBR * DIMF];

// ---------------- helpers ----------------
__device__ __forceinline__ uint32_t f2tf32(float x) {
    uint32_t u;
    asm("cvt.rna.tf32.f32 %0, %1;" : "=r"(u) : "f"(x));
    return u;
}
__device__ __forceinline__ float rnd1(float x) { return __uint_as_float(f2tf32(x)); }
__device__ __forceinline__ float4 rnd4(float4 v) {
    v.x = rnd1(v.x); v.y = rnd1(v.y); v.z = rnd1(v.z); v.w = rnd1(v.w);
    return v;
}
__device__ __forceinline__ void ldsm4(uint32_t a, uint32_t r[4]) {
    asm volatile("ldmatrix.sync.aligned.m8n8.x4.shared.b16 {%0,%1,%2,%3}, [%4];"
                 : "=r"(r[0]), "=r"(r[1]), "=r"(r[2]), "=r"(r[3]) : "r"(a));
}
__device__ __forceinline__ void cpa16(uint32_t dst, const void* src) {
    asm volatile("cp.async.cg.shared.global [%0], [%1], 16;" :: "r"(dst), "l"(src));
}

// =====================================================================
// att_cp: out[m][b][o] = sum_k A[b][k]*B[o][k] (+ bias[m][o])
// Two K-segments (seg0: K0 cols, seg1: rest) with independent pointers.
// Used twice: att_g (K0=0, A1=g, B1=gfcsB raw) and att_z (K0=K, A0=fea_z, B0=Wc).
// Tile 256x128x32, 512 threads (warps 4x4, warp tile 64x32),
// 4-stage cp.async pipeline, XOR-swizzled 128B smem rows, ldmatrix feeds.
// =====================================================================
#define AT_STAGE 49152          // 32768 (A) + 16384 (B) bytes per stage
__global__ __launch_bounds__(512) void att_cp(
    const float* __restrict__ A0, int lda0,
    const float* __restrict__ A1, int lda1, long sA1z,
    int K0, int KT,
    const float* __restrict__ B0, int ldb0, long sB0z,
    const float* __restrict__ B1, int ldb1, long sB1z,
    const float* __restrict__ bias,
    float* __restrict__ outp)
{
    extern __shared__ char smraw[];
    const uint32_t sbase = (uint32_t)__cvta_generic_to_shared(smraw);
    const int tid = threadIdx.x;
    const int m  = blockIdx.z;
    const int bm = blockIdx.y * 256;
    const int bn = blockIdx.x * 128;

    if (A1) A1 += (size_t)m * sA1z;
    if (B0) B0 += (size_t)m * sB0z;
    if (B1) B1 += (size_t)m * sB1z;
    if (bias) bias += (size_t)m * DIMF;
    outp += (size_t)m * BSZ * DIMF;

    const int arow = tid >> 3;          // A rows at +0,+64,+128,+192
    const int ach  = tid & 7;           // 16B chunk within 128B row

    auto issue = [&](int kt) {
        const int s = kt & 3;
        const uint32_t Ab = sbase + s * AT_STAGE;
        const uint32_t Bb = Ab + 32768;
        const int kb = kt * 32;
        const bool seg0 = kb < K0;
        const int ca = seg0 ? (kb + ach * 4) : (kb - K0 + ach * 4);
#pragma unroll
        for (int i = 0; i < 4; i++) {
            const int row = arow + i * 64;
            const float* src = seg0 ? (A0 + (size_t)(bm + row) * lda0 + ca)
                                    : (A1 + (size_t)(bm + row) * lda1 + ca);
            cpa16(Ab + row * 128 + ((ach ^ (row & 7)) * 16), src);
        }
#pragma unroll
        for (int i = 0; i < 2; i++) {
            const int row = (tid >> 3) + i * 64;   // 0..127
            const float* src = seg0 ? (B0 + (size_t)(bn + row) * ldb0 + ca)
                                    : (B1 + (size_t)(bn + row) * ldb1 + ca);
            cpa16(Bb + row * 128 + ((ach ^ (row & 7)) * 16), src);
        }
        asm volatile("cp.async.commit_group;" ::: "memory");
    };

    const int warp = tid >> 5, lane = tid & 31;
    const int wm = warp & 3, wn = warp >> 2;
    const int lr = lane >> 2, lc = lane & 3;

    const int l7 = lane & 7;
    const int a_row_base = wm * 64 + ((lane >> 3) & 1) * 8 + l7;
    const int b_row_base = wn * 32 + (lane >> 4) * 8 + l7;
    const int a_chsel = (lane >> 4);
    const int b_chsel = ((lane >> 3) & 1);

    float c[4][4][4];
#pragma unroll
    for (int a = 0; a < 4; a++)
#pragma unroll
        for (int b = 0; b < 4; b++)
#pragma unroll
            for (int d = 0; d < 4; d++) c[a][b][d] = 0.f;

    issue(0);
    issue(1);
    issue(2);

    for (int kt = 0; kt < KT; kt++) {
        if (kt + 2 <= KT - 1)
            asm volatile("cp.async.wait_group 2;" ::: "memory");
        else if (kt + 1 <= KT - 1)
            asm volatile("cp.async.wait_group 1;" ::: "memory");
        else
            asm volatile("cp.async.wait_group 0;" ::: "memory");
        __syncthreads();

        if (kt + 3 < KT) issue(kt + 3);   // early issue: loads fly during MMAs

        const int s = kt & 3;
        const uint32_t Ab = sbase + s * AT_STAGE;
        const uint32_t Bb = Ab + 32768;
#pragma unroll
        for (int ks = 0; ks < 4; ks++) {
            uint32_t af[4][4];
#pragma unroll
            for (int mi = 0; mi < 4; mi++) {
                const int row = a_row_base + mi * 16;
                ldsm4(Ab + row * 128 + (((ks * 2 + a_chsel) ^ l7) * 16), af[mi]);
            }
            uint32_t bf[2][4];
#pragma unroll
            for (int np = 0; np < 2; np++) {
                const int row = b_row_base + np * 16;
                ldsm4(Bb + row * 128 + (((ks * 2 + b_chsel) ^ l7) * 16), bf[np]);
            }
#pragma unroll
            for (int np = 0; np < 2; np++)
#pragma unroll
                for (int sb = 0; sb < 2; sb++) {
                    const int ni = np * 2 + sb;
#pragma unroll
                    for (int mi = 0; mi < 4; mi++)
                        asm volatile(
                            "mma.sync.aligned.m16n8k8.row.col.f32.tf32.tf32.f32 "
                            "{%0,%1,%2,%3},{%4,%5,%6,%7},{%8,%9},{%0,%1,%2,%3};\n"
                            : "+f"(c[mi][ni][0]), "+f"(c[mi][ni][1]),
                              "+f"(c[mi][ni][2]), "+f"(c[mi][ni][3])
                            : "r"(af[mi][0]), "r"(af[mi][1]),
                              "r"(af[mi][2]), "r"(af[mi][3]),
                              "r"(bf[np][2 * sb]), "r"(bf[np][2 * sb + 1]));
                }
        }
    }

    // epilogue: optional bias + store (float2)
    float bl[4][2];
#pragma unroll
    for (int ni = 0; ni < 4; ni++) {
        const int col = bn + wn * 32 + ni * 8 + 2 * lc;
        bl[ni][0] = bias ? bias[col] : 0.f;
        bl[ni][1] = bias ? bias[col + 1] : 0.f;
    }
#pragma unroll
    for (int mi = 0; mi < 4; mi++) {
        const int row = bm + wm * 64 + mi * 16 + lr;
#pragma unroll
        for (int ni = 0; ni < 4; ni++) {
            const int col = bn + wn * 32 + ni * 8 + 2 * lc;
            float2 v0 = make_float2(c[mi][ni][0] + bl[ni][0], c[mi][ni][1] + bl[ni][1]);
            float2 v1 = make_float2(c[mi][ni][2] + bl[ni][0], c[mi][ni][3] + bl[ni][1]);
            *(float2*)(outp + (size_t)row * DIMF + col) = v0;
            *(float2*)(outp + (size_t)(row + 8) * DIMF + col) = v1;
        }
    }
}

// ---------------- generic tf32 NT GEMM (mma.sync + ldmatrix) ----------------
template<int MODE, int RND, int MI>
__global__ __launch_bounds__(256, 2) void gemm2(
    const float* __restrict__ A0, long sA0z, int lda0, int K0,
    const float* __restrict__ A1, long sA1z, int lda1, int K1,
    const float* __restrict__ B0, long sB0z, int ldb0,
    const float* __restrict__ B1, long sB1z, int ldb1,
    const float* __restrict__ bias, long sBiasZ,
    const float* __restrict__ bng, const float* __restrict__ bnb,
    float* __restrict__ C, long sCz, int N)
{
    const int K  = K0 + K1;
    const int KT = K >> 5;
    constexpr int MROWS = MI * 64;

    extern __shared__ float sm[];
    float* As  = sm;
    float* Bsm = sm + 2 * MROWS * 36;

    const int tid = threadIdx.x;
    const int z   = blockIdx.z;
    A0 += z * sA0z;
    if (A1) A1 += z * sA1z;
    B0 += z * sB0z;
    if (B1) B1 += z * sB1z;
    if (bias) bias += z * sBiasZ;
    C  += z * sCz;

    const int bm = blockIdx.y * MROWS;
    const int bn = blockIdx.x * 128;

    const int lrow = tid >> 3;
    const int c4   = (tid & 7) * 4;

    float4 a_stg[2 * MI], b_stg[4];

    auto ldTiles = [&](int kt) {
        const int gk = kt * 32 + c4;
#pragma unroll
        for (int i = 0; i < 2 * MI; i++) {
            const int row = lrow + i * 32;
            const float* s = (gk < K0) ? (A0 + (long)(bm + row) * lda0 + gk)
                                       : (A1 + (long)(bm + row) * lda1 + (gk - K0));
            a_stg[i] = *(const float4*)s;
        }
#pragma unroll
        for (int i = 0; i < 4; i++) {
            const int row = lrow + i * 32;
            int j = bn + row; if (j > N - 1) j = N - 1;
            const float* s = (gk < K0) ? (B0 + (long)j * ldb0 + gk)
                                       : (B1 + (long)j * ldb1 + (gk - K0));
            b_stg[i] = *(const float4*)s;
        }
    };
    auto stTiles = [&](int buf) {
        float* a = As  + buf * MROWS * 36;
        float* b = Bsm + buf * 128 * 36;
#pragma unroll
        for (int i = 0; i < 2 * MI; i++)
            *(float4*)(a + (lrow + i * 32) * 36 + c4) = rnd4(a_stg[i]);
#pragma unroll
        for (int i = 0; i < 4; i++)
            *(float4*)(b + (lrow + i * 32) * 36 + c4) = rnd4(b_stg[i]);
    };

    float c[MI][8][4];
#pragma unroll
    for (int a = 0; a < MI; a++)
#pragma unroll
        for (int b2 = 0; b2 < 8; b2++)
#pragma unroll
            for (int d = 0; d < 4; d++) c[a][b2][d] = 0.f;

    const int warp = tid >> 5, lane = tid & 31;
    const int wm = warp & 3, wn = warp >> 2;
    const int lr = lane >> 2, lc = lane & 3;

    const int a_row = wm * (MI * 16) + ((lane >> 3) & 1) * 8 + (lane & 7);
    const int a_col = (lane >> 4) * 4;
    const uint32_t aoff = (uint32_t)((a_row * 36 + a_col) * 4);
    const int b_row = wn * 64 + (lane >> 4) * 8 + (lane & 7);
    const int b_col = ((lane >> 3) & 1) * 4;
    const uint32_t boff = (uint32_t)((b_row * 36 + b_col) * 4);

    const uint32_t sA = (uint32_t)__cvta_generic_to_shared(As);
    const uint32_t sB = (uint32_t)__cvta_generic_to_shared(Bsm);
    const uint32_t ABUF = MROWS * 36 * 4;
    const uint32_t BBUF = 128 * 36 * 4;

    ldTiles(0);
    stTiles(0);
    __syncthreads();

    for (int kt = 0; kt < KT; kt++) {
        const bool has_next = (kt + 1 < KT);
        if (has_next) ldTiles(kt + 1);

        const uint32_t aBuf = sA + (kt & 1) * ABUF + aoff;
        const uint32_t bBuf = sB + (kt & 1) * BBUF + boff;
#pragma unroll
        for (int ks = 0; ks < 4; ks++) {
            const uint32_t kByte = (uint32_t)(ks * 8 * 4);
            uint32_t af[MI][4];
#pragma unroll
            for (int mi = 0; mi < MI; mi++)
                ldsm4(aBuf + mi * (16 * 36 * 4) + kByte, af[mi]);
            uint32_t bf[4][4];
#pragma unroll
            for (int np = 0; np < 4; np++)
                ldsm4(bBuf + np * (16 * 36 * 4) + kByte, bf[np]);
#pragma unroll
            for (int np = 0; np < 4; np++)
#pragma unroll
                for (int s = 0; s < 2; s++) {
                    const int ni = np * 2 + s;
#pragma unroll
                    for (int mi = 0; mi < MI; mi++)
                        asm volatile(
                            "mma.sync.aligned.m16n8k8.row.col.f32.tf32.tf32.f32 "
                            "{%0,%1,%2,%3},{%4,%5,%6,%7},{%8,%9},{%0,%1,%2,%3};\n"
                            : "+f"(c[mi][ni][0]), "+f"(c[mi][ni][1]),
                              "+f"(c[mi][ni][2]), "+f"(c[mi][ni][3])
                            : "r"(af[mi][0]), "r"(af[mi][1]),
                              "r"(af[mi][2]), "r"(af[mi][3]),
                              "r"(bf[np][2 * s]), "r"(bf[np][2 * s + 1]));
                }
        }
        if (has_next) stTiles((kt + 1) & 1);
        __syncthreads();
    }

    const float inv = rsqrtf(1.0f + 1e-5f);
#pragma unroll
    for (int mi = 0; mi < MI; mi++) {
        const int row = bm + wm * (MI * 16) + mi * 16 + lr;
#pragma unroll
        for (int ni = 0; ni < 8; ni++) {
            const int col = bn + wn * 64 + ni * 8 + 2 * lc;
#pragma unroll
            for (int h = 0; h < 2; h++) {
                const int r = row + h * 8;
#pragma unroll
                for (int q = 0; q < 2; q++) {
                    const int j = col + q;
                    if (j < N) {
                        float v = c[mi][ni][h * 2 + q];
                        if (bias) v += bias[j];
                        if (MODE == 1) v = fmaxf(v, 0.f) * bng[j] * inv + bnb[j];
                        if (RND) v = rnd1(v);
                        C[(long)r * N + j] = v;
                    }
                }
            }
        }
    }
}

// ---------------- fea_u = sum over the 19 branches of x (float4) ----------------
__global__ void reduce_x(const float* __restrict__ x, float* __restrict__ out) {
    long idx = (long)blockIdx.x * blockDim.x + threadIdx.x;
    if (idx >= (long)BSZ * DIMF / 4) return;
    int b  = (int)(idx / (DIMF / 4));
    int d4 = (int)(idx % (DIMF / 4));
    const float4* p = (const float4*)(x + (size_t)b * XROW) + d4;
    float4 s = make_float4(0.f, 0.f, 0.f, 0.f);
#pragma unroll
    for (int mm = 0; mm < NBR; mm++) {
        float4 v = p[mm * (DIMF / 4)];
        s.x += v.x; s.y += v.y; s.z += v.z; s.w += v.w;
    }
    ((float4*)out)[idx] = s;
}

// ---------------- setup: transpose fcs_W  +  folded bias (merged) ----------------
__global__ void setup_misc(const float* __restrict__ fcsW, float* __restrict__ fcsT,
                           const float* __restrict__ gfcsW, const float* __restrict__ gfcsB,
                           const float* __restrict__ fcsB, float* __restrict__ bc)
{
    const int m = blockIdx.z;
    if (blockIdx.y < 12) {
        __shared__ float t[32][33];
        const int i0 = blockIdx.y * 32, d0 = blockIdx.x * 32;
        const float* src = fcsW + (size_t)m * DD * DD;
        float* dst       = fcsT + (size_t)m * DD * DD;
        const int x = threadIdx.x, y = threadIdx.y;
#pragma unroll
        for (int yy = y; yy < 32; yy += 8)
            t[yy][x] = src[(size_t)(i0 + yy) * DD + d0 + x];
        __syncthreads();
#pragma unroll
        for (int yy = y; yy < 32; yy += 8)
            dst[(size_t)(d0 + yy) * DD + i0 + x] = t[x][yy];
    } else {
        const int tid = threadIdx.y * 32 + threadIdx.x;
        const int w = tid >> 5, lane = tid & 31;
        const float* fb = fcsB + m * DD;
        for (int j = 0; j < 8; j++) {
            const int o = blockIdx.x * 64 + w * 8 + j;
            const float* wp = gfcsW + ((size_t)m * DIMF + o) * GW;
            float s = 0.f;
            for (int i = lane; i < DD; i += 32) s += wp[i] * fb[i];
#pragma unroll
            for (int off = 16; off; off >>= 1) s += __shfl_xor_sync(0xffffffffu, s, off);
            if (lane == 0) bc[(size_t)m * DIMF + o] = s + gfcsB[(size_t)m * DIMF + o];
        }
    }
}

// ---------------- softmax over m (sum of two logit buffers) + weighted sum ----------------
__global__ void softmax_wsum(const float* __restrict__ att1,
                             const float* __restrict__ att2,
                             const float* __restrict__ x,
                             float* __restrict__ out) {
    long idx = (long)blockIdx.x * blockDim.x + threadIdx.x;
    if (idx >= (long)BSZ * DIMF / 4) return;
    int b  = (int)(idx / (DIMF / 4));
    int o4 = (int)(idx % (DIMF / 4));

    float4 v[NBR];
    float4 mx = make_float4(-1e30f, -1e30f, -1e30f, -1e30f);
#pragma unroll
    for (int mm = 0; mm < NBR; mm++) {
        float4 a = *((const float4*)(att1 + ((size_t)mm * BSZ + b) * DIMF) + o4);
        float4 bb = *((const float4*)(att2 + ((size_t)mm * BSZ + b) * DIMF) + o4);
        v[mm] = make_float4(a.x + bb.x, a.y + bb.y, a.z + bb.z, a.w + bb.w);
        mx.x = fmaxf(mx.x, v[mm].x); mx.y = fmaxf(mx.y, v[mm].y);
        mx.z = fmaxf(mx.z, v[mm].z); mx.w = fmaxf(mx.w, v[mm].w);
    }
    float4 s = make_float4(0.f, 0.f, 0.f, 0.f);
#pragma unroll
    for (int mm = 0; mm < NBR; mm++) {
        v[mm].x = __expf(v[mm].x - mx.x); s.x += v[mm].x;
        v[mm].y = __expf(v[mm].y - mx.y); s.y += v[mm].y;
        v[mm].z = __expf(v[mm].z - mx.z); s.z += v[mm].z;
        v[mm].w = __expf(v[mm].w - mx.w); s.w += v[mm].w;
    }
    s.x = 1.f / s.x; s.y = 1.f / s.y; s.z = 1.f / s.z; s.w = 1.f / s.w;
    float4 acc = make_float4(0.f, 0.f, 0.f, 0.f);
    const float4* xp = (const float4*)(x + (size_t)b * XROW) + o4;
#pragma unroll
    for (int mm = 0; mm < NBR; mm++) {
        float4 xv = xp[mm * (DIMF / 4)];
        acc.x += v[mm].x * s.x * xv.x;
        acc.y += v[mm].y * s.y * xv.y;
        acc.z += v[mm].z * s.z * xv.z;
        acc.w += v[mm].w * s.w * xv.w;
    }
    ((float4*)out)[idx] = acc;
}

// ---------------- launch ----------------
extern "C" void kernel_launch(void* const* d_in, const int* in_sizes, int n_in,
                              void* d_out, int out_size) {
    const float* x      = (const float*)d_in[0];
    const float* g      = (const float*)d_in[1];
    const float* fc1_W  = (const float*)d_in[2];
    const float* fc1_b  = (const float*)d_in[3];
    const float* bn1_g  = (const float*)d_in[4];
    const float* bn1_b  = (const float*)d_in[5];
    const float* fc2_W  = (const float*)d_in[6];
    const float* fc2_b  = (const float*)d_in[7];
    const float* fcs_W  = (const float*)d_in[8];
    const float* fcs_b  = (const float*)d_in[9];
    const float* gfcs_W = (const float*)d_in[10];
    const float* gfcs_b = (const float*)d_in[11];
    const float* l1_W   = (const float*)d_in[12];
    const float* l1_b   = (const float*)d_in[13];
    const float* bna_g  = (const float*)d_in[14];
    const float* bna_b  = (const float*)d_in[15];
    const float* l2_W   = (const float*)d_in[16];
    const float* l2_b   = (const float*)d_in[17];
    const float* bnb_g  = (const float*)d_in[18];
    const float* bnb_b  = (const float*)d_in[19];
    const float* l3_W   = (const float*)d_in[20];
    const float* l3_b   = (const float*)d_in[21];
    float* out = (float*)d_out;

    float *fea_u, *h1, *fea_z, *att, *att2, *fea_v, *hA, *hB, *Wc, *fcsT, *bc;
    cudaGetSymbolAddress((void**)&fea_u, g_fea_u);
    cudaGetSymbolAddress((void**)&h1,    g_h1);
    cudaGetSymbolAddress((void**)&fea_z, g_fea_z);
    cudaGetSymbolAddress((void**)&att,   g_att);
    cudaGetSymbolAddress((void**)&att2,  g_att2);
    cudaGetSymbolAddress((void**)&fea_v, g_fea_v);
    cudaGetSymbolAddress((void**)&hA,    g_hA);
    cudaGetSymbolAddress((void**)&hB,    g_hB);
    cudaGetSymbolAddress((void**)&Wc,    g_Wc);
    cudaGetSymbolAddress((void**)&fcsT,  g_fcsT);
    cudaGetSymbolAddress((void**)&bc,    g_bc);

    const int SMEM2  = 2 * (128 + 128) * 36 * 4;   // MI=2: 73728 B
    const int SMEM1  = 2 * (64 + 128) * 36 * 4;    // MI=1: 55296 B
    const int ASMEM  = 4 * AT_STAGE;               // att_cp: 196608 B
    cudaFuncSetAttribute(gemm2<0,0,1>, cudaFuncAttributeMaxDynamicSharedMemorySize, SMEM1);
    cudaFuncSetAttribute(gemm2<0,1,1>, cudaFuncAttributeMaxDynamicSharedMemorySize, SMEM1);
    cudaFuncSetAttribute(gemm2<1,0,1>, cudaFuncAttributeMaxDynamicSharedMemorySize, SMEM1);
    cudaFuncSetAttribute(gemm2<0,1,2>, cudaFuncAttributeMaxDynamicSharedMemorySize, SMEM2);
    cudaFuncSetAttribute(att_cp,       cudaFuncAttributeMaxDynamicSharedMemorySize, ASMEM);

    // ---- fork side streams (graph-capture legal) ----
    cudaStream_t s2, s3;
    cudaStreamCreateWithFlags(&s2, cudaStreamNonBlocking);
    cudaStreamCreateWithFlags(&s3, cudaStreamNonBlocking);
    cudaEvent_t e0, e1, e2;
    cudaEventCreateWithFlags(&e0, cudaEventDisableTiming);
    cudaEventCreateWithFlags(&e1, cudaEventDisableTiming);
    cudaEventCreateWithFlags(&e2, cudaEventDisableTiming);

    cudaEventRecord(e0, 0);
    cudaStreamWaitEvent(s2, e0, 0);
    cudaStreamWaitEvent(s3, e0, 0);

    // --- branch S3: att_g = g @ gfcsB^T (no dependencies; bulk of the FLOPs) ---
    att_cp<<<dim3(6, 16, NBR), 512, ASMEM, s3>>>(
        nullptr, 0,
        g, XROW, (long)DIMF,
        0 /*K0*/, DIMF / 32 /*KT=24*/,
        nullptr, 0, 0,
        gfcs_W + DD, GW, (long)DIMF * GW,
        nullptr, att2);
    cudaEventRecord(e2, s3);

    // --- branch S2: weight prep (setup_misc -> Wc fold) ---
    setup_misc<<<dim3(12, 13, NBR), dim3(32, 8), 0, s2>>>(fcs_W, fcsT, gfcs_W, gfcs_b, fcs_b, bc);
    gemm2<0,1,2><<<dim3(3, 6, NBR), 256, SMEM2, s2>>>(
        gfcs_W, (long)DIMF * GW, GW, DD,  nullptr, 0, 0, 0,
        fcsT, (long)DD * DD, DD,  nullptr, 0, 0,
        nullptr, 0, nullptr, nullptr,
        Wc, (long)DIMF * DD, DD);
    cudaEventRecord(e1, s2);

    // --- main stream: activation chain ---
    reduce_x<<<(BSZ * DIMF / 4 + 255) / 256, 256>>>(x, fea_u);

    gemm2<1,0,1><<<dim3(3, 64, 1), 256, SMEM1>>>(
        fea_u, 0, DIMF, DIMF,  nullptr, 0, 0, 0,
        fc1_W, 0, DIMF,  nullptr, 0, 0,
        fc1_b, 0, bn1_g, bn1_b, h1, 0, DD);

    gemm2<0,1,1><<<dim3(3, 64, 1), 256, SMEM1>>>(
        h1, 0, DD, DD,  nullptr, 0, 0, 0,
        fc2_W, 0, DD,  nullptr, 0, 0,
        fc2_b, 0, nullptr, nullptr, fea_z, 0, DD);

    // join: att_z needs Wc/bc from s2
    cudaStreamWaitEvent(0, e1, 0);

    // att_z = fea_z @ Wc^T + bc  (K=384)
    att_cp<<<dim3(6, 16, NBR), 512, ASMEM>>>(
        fea_z, DD,
        nullptr, 0, 0,
        DD /*K0*/, DD / 32 /*KT=12*/,
        Wc, DD, (long)DIMF * DD,
        nullptr, 0, 0,
        bc, att);

    // join: softmax needs att_g from s3
    cudaStreamWaitEvent(0, e2, 0);

    // softmax over m (att + att2) + weighted sum with x
    softmax_wsum<<<(BSZ * DIMF / 4 + 255) / 256, 256>>>(att, att2, x, fea_v);

    // classifier head
    gemm2<1,0,1><<<dim3(1, 64, 1), 256, SMEM1>>>(
        fea_v, 0, DIMF, DIMF,  nullptr, 0, 0, 0,
        l1_W, 0, DIMF,  nullptr, 0, 0,
        l1_b, 0, bna_g, bna_b, hA, 0, 128);

    gemm2<1,0,1><<<dim3(1, 64, 1), 256, SMEM1>>>(
        hA, 0, 128, 128,  nullptr, 0, 0, 0,
        l2_W, 0, 128,  nullptr, 0, 0,
        l2_b, 0, bnb_g, bnb_b, hB, 0, 32);

    gemm2<0,0,1><<<dim3(1, 64, 1), 256, SMEM1>>>(
        hB, 0, 32, 32,  nullptr, 0, 0, 0,
        l3_W, 0, 32,  nullptr, 0, 0,
        l3_b, 0, nullptr, nullptr, out, 0, 20);

    cudaEventDestroy(e0);
    cudaEventDestroy(e1);
    cudaEventDestroy(e2);
    cudaStreamDestroy(s2);
    cudaStreamDestroy(s3);
}

// round 13
// speedup vs baseline: 1.1319x; 1.1319x over previous
#include <cuda_runtime.h>
#include <cuda_fp16.h>
#include <cstdint>

#define NBR   19
#define DIMF  768
#define DD    384
#define BSZ   4096
#define XROW  (NBR * DIMF)   // 14592
#define GW    (DIMF + DD)    // 1152

// ---------------- scratch (device globals) ----------------
__device__ float  g_fea_u[(size_t)BSZ * DIMF];
__device__ float  g_h1[(size_t)BSZ * DD];
__device__ float  g_fea_z[(size_t)BSZ * DD];
__device__ __half g_att[(size_t)NBR * BSZ * DIMF];   // fp16 logits
__device__ float  g_fea_v[(size_t)BSZ * DIMF];
__device__ float  g_hA[(size_t)BSZ * 128];
__device__ float  g_Wc[(size_t)NBR * DIMF * DD];
__device__ float  g_fcsT[(size_t)NBR * DD * DD];
__device__ float  g_bc[(size_t)NBR * DIMF];

// ---------------- helpers ----------------
__device__ __forceinline__ uint32_t f2tf32(float x) {
    uint32_t u;
    asm("cvt.rna.tf32.f32 %0, %1;" : "=r"(u) : "f"(x));
    return u;
}
__device__ __forceinline__ float rnd1(float x) { return __uint_as_float(f2tf32(x)); }
__device__ __forceinline__ float4 rnd4(float4 v) {
    v.x = rnd1(v.x); v.y = rnd1(v.y); v.z = rnd1(v.z); v.w = rnd1(v.w);
    return v;
}
__device__ __forceinline__ void ldsm4(uint32_t a, uint32_t r[4]) {
    asm volatile("ldmatrix.sync.aligned.m8n8.x4.shared.b16 {%0,%1,%2,%3}, [%4];"
                 : "=r"(r[0]), "=r"(r[1]), "=r"(r[2]), "=r"(r[3]) : "r"(a));
}
__device__ __forceinline__ void cpa16(uint32_t dst, const void* src) {
    asm volatile("cp.async.cg.shared.global [%0], [%1], 16;" :: "r"(dst), "l"(src));
}

// =====================================================================
// att_cp (R11 structure): att[m][b][o] = sum_k A[b][k]*B[o][k] + bc[m][o]
//   A = [fea_z (384, RNA-rounded) | g[:,m,:] (768, raw -> HW truncation)]
//   B = [Wc[m] (384, rounded) | gfcsB slice of gfcs_W (768, raw -> HW truncation)]
// Tile 256x128x32, 512 threads (warps 4x4, warp tile 64x32),
// 4-stage cp.async pipeline, XOR-swizzled 128B smem rows, ldmatrix feeds.
// Output stored as fp16 (logits; softmax consumes once).
// =====================================================================
#define AT_STAGE 49152          // 32768 (A) + 16384 (B) bytes per stage
__global__ __launch_bounds__(512) void att_cp(
    const float* __restrict__ fea_z,
    const float* __restrict__ g,
    const float* __restrict__ Wc,
    const float* __restrict__ WB,      // row stride ldb1
    int ldb1,
    const float* __restrict__ bc,
    __half* __restrict__ att)
{
    extern __shared__ char smraw[];
    const uint32_t sbase = (uint32_t)__cvta_generic_to_shared(smraw);
    const int tid = threadIdx.x;
    const int m  = blockIdx.z;
    const int bm = blockIdx.y * 256;
    const int bn = blockIdx.x * 128;

    const float* A1 = g + (size_t)m * DIMF;
    const float* B0 = Wc + (size_t)m * DIMF * DD;
    const float* B1 = WB + (size_t)m * DIMF * ldb1;

    const int arow = tid >> 3;          // A rows at +0,+64,+128,+192
    const int ach  = tid & 7;           // 16B chunk within 128B row
    const int KT = GW / 32;             // 36

    auto issue = [&](int kt) {
        const int s = kt & 3;
        const uint32_t Ab = sbase + s * AT_STAGE;
        const uint32_t Bb = Ab + 32768;
        const int kb = kt * 32;
        const bool seg0 = kb < DD;
        const int ca = seg0 ? (kb + ach * 4) : (kb - DD + ach * 4);
#pragma unroll
        for (int i = 0; i < 4; i++) {
            const int row = arow + i * 64;
            const float* src = seg0 ? (fea_z + (size_t)(bm + row) * DD + ca)
                                    : (A1 + (size_t)(bm + row) * XROW + ca);
            cpa16(Ab + row * 128 + ((ach ^ (row & 7)) * 16), src);
        }
#pragma unroll
        for (int i = 0; i < 2; i++) {
            const int row = (tid >> 3) + i * 64;   // 0..127
            const float* src = seg0 ? (B0 + (size_t)(bn + row) * DD + ca)
                                    : (B1 + (size_t)(bn + row) * ldb1 + ca);
            cpa16(Bb + row * 128 + ((ach ^ (row & 7)) * 16), src);
        }
        asm volatile("cp.async.commit_group;" ::: "memory");
    };

    const int warp = tid >> 5, lane = tid & 31;
    const int wm = warp & 3, wn = warp >> 2;
    const int lr = lane >> 2, lc = lane & 3;

    const int l7 = lane & 7;
    const int a_row_base = wm * 64 + ((lane >> 3) & 1) * 8 + l7;
    const int b_row_base = wn * 32 + (lane >> 4) * 8 + l7;
    const int a_chsel = (lane >> 4);
    const int b_chsel = ((lane >> 3) & 1);

    float c[4][4][4];
#pragma unroll
    for (int a = 0; a < 4; a++)
#pragma unroll
        for (int b = 0; b < 4; b++)
#pragma unroll
            for (int d = 0; d < 4; d++) c[a][b][d] = 0.f;

    issue(0);
    issue(1);
    issue(2);

    for (int kt = 0; kt < KT; kt++) {
        if (kt + 2 <= KT - 1)
            asm volatile("cp.async.wait_group 2;" ::: "memory");
        else if (kt + 1 <= KT - 1)
            asm volatile("cp.async.wait_group 1;" ::: "memory");
        else
            asm volatile("cp.async.wait_group 0;" ::: "memory");
        __syncthreads();

        if (kt + 3 < KT) issue(kt + 3);   // early issue: loads fly during MMAs

        const int s = kt & 3;
        const uint32_t Ab = sbase + s * AT_STAGE;
        const uint32_t Bb = Ab + 32768;
#pragma unroll
        for (int ks = 0; ks < 4; ks++) {
            uint32_t af[4][4];
#pragma unroll
            for (int mi = 0; mi < 4; mi++) {
                const int row = a_row_base + mi * 16;
                ldsm4(Ab + row * 128 + (((ks * 2 + a_chsel) ^ l7) * 16), af[mi]);
            }
            uint32_t bf[2][4];
#pragma unroll
            for (int np = 0; np < 2; np++) {
                const int row = b_row_base + np * 16;
                ldsm4(Bb + row * 128 + (((ks * 2 + b_chsel) ^ l7) * 16), bf[np]);
            }
#pragma unroll
            for (int np = 0; np < 2; np++)
#pragma unroll
                for (int sb = 0; sb < 2; sb++) {
                    const int ni = np * 2 + sb;
#pragma unroll
                    for (int mi = 0; mi < 4; mi++)
                        asm volatile(
                            "mma.sync.aligned.m16n8k8.row.col.f32.tf32.tf32.f32 "
                            "{%0,%1,%2,%3},{%4,%5,%6,%7},{%8,%9},{%0,%1,%2,%3};\n"
                            : "+f"(c[mi][ni][0]), "+f"(c[mi][ni][1]),
                              "+f"(c[mi][ni][2]), "+f"(c[mi][ni][3])
                            : "r"(af[mi][0]), "r"(af[mi][1]),
                              "r"(af[mi][2]), "r"(af[mi][3]),
                              "r"(bf[np][2 * sb]), "r"(bf[np][2 * sb + 1]));
                }
        }
    }

    // epilogue: bias + fp16 store
    float bl[4][2];
#pragma unroll
    for (int ni = 0; ni < 4; ni++) {
        const int col = bn + wn * 32 + ni * 8 + 2 * lc;
        bl[ni][0] = bc[(size_t)m * DIMF + col];
        bl[ni][1] = bc[(size_t)m * DIMF + col + 1];
    }
    __half* Cm = att + (size_t)m * BSZ * DIMF;
#pragma unroll
    for (int mi = 0; mi < 4; mi++) {
        const int row = bm + wm * 64 + mi * 16 + lr;
#pragma unroll
        for (int ni = 0; ni < 4; ni++) {
            const int col = bn + wn * 32 + ni * 8 + 2 * lc;
            __half2 v0 = __floats2half2_rn(c[mi][ni][0] + bl[ni][0], c[mi][ni][1] + bl[ni][1]);
            __half2 v1 = __floats2half2_rn(c[mi][ni][2] + bl[ni][0], c[mi][ni][3] + bl[ni][1]);
            *(__half2*)(Cm + (size_t)row * DIMF + col) = v0;
            *(__half2*)(Cm + (size_t)(row + 8) * DIMF + col) = v1;
        }
    }
}

// ---------------- generic tf32 NT GEMM (mma.sync + ldmatrix) ----------------
template<int MODE, int RND, int MI>
__global__ __launch_bounds__(256, 2) void gemm2(
    const float* __restrict__ A0, long sA0z, int lda0, int K0,
    const float* __restrict__ A1, long sA1z, int lda1, int K1,
    const float* __restrict__ B0, long sB0z, int ldb0,
    const float* __restrict__ B1, long sB1z, int ldb1,
    const float* __restrict__ bias, long sBiasZ,
    const float* __restrict__ bng, const float* __restrict__ bnb,
    float* __restrict__ C, long sCz, int N)
{
    const int K  = K0 + K1;
    const int KT = K >> 5;
    constexpr int MROWS = MI * 64;

    extern __shared__ float sm[];
    float* As  = sm;
    float* Bsm = sm + 2 * MROWS * 36;

    const int tid = threadIdx.x;
    const int z   = blockIdx.z;
    A0 += z * sA0z;
    if (A1) A1 += z * sA1z;
    B0 += z * sB0z;
    if (B1) B1 += z * sB1z;
    if (bias) bias += z * sBiasZ;
    C  += z * sCz;

    const int bm = blockIdx.y * MROWS;
    const int bn = blockIdx.x * 128;

    const int lrow = tid >> 3;
    const int c4   = (tid & 7) * 4;

    float4 a_stg[2 * MI], b_stg[4];

    auto ldTiles = [&](int kt) {
        const int gk = kt * 32 + c4;
#pragma unroll
        for (int i = 0; i < 2 * MI; i++) {
            const int row = lrow + i * 32;
            const float* s = (gk < K0) ? (A0 + (long)(bm + row) * lda0 + gk)
                                       : (A1 + (long)(bm + row) * lda1 + (gk - K0));
            a_stg[i] = *(const float4*)s;
        }
#pragma unroll
        for (int i = 0; i < 4; i++) {
            const int row = lrow + i * 32;
            int j = bn + row; if (j > N - 1) j = N - 1;
            const float* s = (gk < K0) ? (B0 + (long)j * ldb0 + gk)
                                       : (B1 + (long)j * ldb1 + (gk - K0));
            b_stg[i] = *(const float4*)s;
        }
    };
    auto stTiles = [&](int buf) {
        float* a = As  + buf * MROWS * 36;
        float* b = Bsm + buf * 128 * 36;
#pragma unroll
        for (int i = 0; i < 2 * MI; i++)
            *(float4*)(a + (lrow + i * 32) * 36 + c4) = rnd4(a_stg[i]);
#pragma unroll
        for (int i = 0; i < 4; i++)
            *(float4*)(b + (lrow + i * 32) * 36 + c4) = rnd4(b_stg[i]);
    };

    float c[MI][8][4];
#pragma unroll
    for (int a = 0; a < MI; a++)
#pragma unroll
        for (int b2 = 0; b2 < 8; b2++)
#pragma unroll
            for (int d = 0; d < 4; d++) c[a][b2][d] = 0.f;

    const int warp = tid >> 5, lane = tid & 31;
    const int wm = warp & 3, wn = warp >> 2;
    const int lr = lane >> 2, lc = lane & 3;

    const int a_row = wm * (MI * 16) + ((lane >> 3) & 1) * 8 + (lane & 7);
    const int a_col = (lane >> 4) * 4;
    const uint32_t aoff = (uint32_t)((a_row * 36 + a_col) * 4);
    const int b_row = wn * 64 + (lane >> 4) * 8 + (lane & 7);
    const int b_col = ((lane >> 3) & 1) * 4;
    const uint32_t boff = (uint32_t)((b_row * 36 + b_col) * 4);

    const uint32_t sA = (uint32_t)__cvta_generic_to_shared(As);
    const uint32_t sB = (uint32_t)__cvta_generic_to_shared(Bsm);
    const uint32_t ABUF = MROWS * 36 * 4;
    const uint32_t BBUF = 128 * 36 * 4;

    ldTiles(0);
    stTiles(0);
    __syncthreads();

    for (int kt = 0; kt < KT; kt++) {
        const bool has_next = (kt + 1 < KT);
        if (has_next) ldTiles(kt + 1);

        const uint32_t aBuf = sA + (kt & 1) * ABUF + aoff;
        const uint32_t bBuf = sB + (kt & 1) * BBUF + boff;
#pragma unroll
        for (int ks = 0; ks < 4; ks++) {
            const uint32_t kByte = (uint32_t)(ks * 8 * 4);
            uint32_t af[MI][4];
#pragma unroll
            for (int mi = 0; mi < MI; mi++)
                ldsm4(aBuf + mi * (16 * 36 * 4) + kByte, af[mi]);
            uint32_t bf[4][4];
#pragma unroll
            for (int np = 0; np < 4; np++)
                ldsm4(bBuf + np * (16 * 36 * 4) + kByte, bf[np]);
#pragma unroll
            for (int np = 0; np < 4; np++)
#pragma unroll
                for (int s = 0; s < 2; s++) {
                    const int ni = np * 2 + s;
#pragma unroll
                    for (int mi = 0; mi < MI; mi++)
                        asm volatile(
                            "mma.sync.aligned.m16n8k8.row.col.f32.tf32.tf32.f32 "
                            "{%0,%1,%2,%3},{%4,%5,%6,%7},{%8,%9},{%0,%1,%2,%3};\n"
                            : "+f"(c[mi][ni][0]), "+f"(c[mi][ni][1]),
                              "+f"(c[mi][ni][2]), "+f"(c[mi][ni][3])
                            : "r"(af[mi][0]), "r"(af[mi][1]),
                              "r"(af[mi][2]), "r"(af[mi][3]),
                              "r"(bf[np][2 * s]), "r"(bf[np][2 * s + 1]));
                }
        }
        if (has_next) stTiles((kt + 1) & 1);
        __syncthreads();
    }

    const float inv = rsqrtf(1.0f + 1e-5f);
#pragma unroll
    for (int mi = 0; mi < MI; mi++) {
        const int row = bm + wm * (MI * 16) + mi * 16 + lr;
#pragma unroll
        for (int ni = 0; ni < 8; ni++) {
            const int col = bn + wn * 64 + ni * 8 + 2 * lc;
#pragma unroll
            for (int h = 0; h < 2; h++) {
                const int r = row + h * 8;
#pragma unroll
                for (int q = 0; q < 2; q++) {
                    const int j = col + q;
                    if (j < N) {
                        float v = c[mi][ni][h * 2 + q];
                        if (bias) v += bias[j];
                        if (MODE == 1) v = fmaxf(v, 0.f) * bng[j] * inv + bnb[j];
                        if (RND) v = rnd1(v);
                        C[(long)r * N + j] = v;
                    }
                }
            }
        }
    }
}

// ---------------- fea_u = sum over the 19 branches of x (float4) ----------------
__global__ void reduce_x(const float* __restrict__ x, float* __restrict__ out) {
    long idx = (long)blockIdx.x * blockDim.x + threadIdx.x;
    if (idx >= (long)BSZ * DIMF / 4) return;
    int b  = (int)(idx / (DIMF / 4));
    int d4 = (int)(idx % (DIMF / 4));
    const float4* p = (const float4*)(x + (size_t)b * XROW) + d4;
    float4 s = make_float4(0.f, 0.f, 0.f, 0.f);
#pragma unroll
    for (int mm = 0; mm < NBR; mm++) {
        float4 v = p[mm * (DIMF / 4)];
        s.x += v.x; s.y += v.y; s.z += v.z; s.w += v.w;
    }
    ((float4*)out)[idx] = s;
}

// ---------------- setup: transpose fcs_W  +  folded bias (merged) ----------------
__global__ void setup_misc(const float* __restrict__ fcsW, float* __restrict__ fcsT,
                           const float* __restrict__ gfcsW, const float* __restrict__ gfcsB,
                           const float* __restrict__ fcsB, float* __restrict__ bc)
{
    const int m = blockIdx.z;
    if (blockIdx.y < 12) {
        __shared__ float t[32][33];
        const int i0 = blockIdx.y * 32, d0 = blockIdx.x * 32;
        const float* src = fcsW + (size_t)m * DD * DD;
        float* dst       = fcsT + (size_t)m * DD * DD;
        const int x = threadIdx.x, y = threadIdx.y;
#pragma unroll
        for (int yy = y; yy < 32; yy += 8)
            t[yy][x] = src[(size_t)(i0 + yy) * DD + d0 + x];
        __syncthreads();
#pragma unroll
        for (int yy = y; yy < 32; yy += 8)
            dst[(size_t)(d0 + yy) * DD + i0 + x] = t[x][yy];
    } else {
        const int tid = threadIdx.y * 32 + threadIdx.x;
        const int w = tid >> 5, lane = tid & 31;
        const float* fb = fcsB + m * DD;
        for (int j = 0; j < 8; j++) {
            const int o = blockIdx.x * 64 + w * 8 + j;
            const float* wp = gfcsW + ((size_t)m * DIMF + o) * GW;
            float s = 0.f;
            for (int i = lane; i < DD; i += 32) s += wp[i] * fb[i];
#pragma unroll
            for (int off = 16; off; off >>= 1) s += __shfl_xor_sync(0xffffffffu, s, off);
            if (lane == 0) bc[(size_t)m * DIMF + o] = s + gfcsB[(size_t)m * DIMF + o];
        }
    }
}

// ---------------- softmax over m (fp16 logits) + weighted sum with x ----------------
__global__ void softmax_wsum(const __half* __restrict__ att,
                             const float* __restrict__ x,
                             float* __restrict__ out) {
    long idx = (long)blockIdx.x * blockDim.x + threadIdx.x;   // 4-wide index
    if (idx >= (long)BSZ * DIMF / 4) return;
    int b  = (int)(idx / (DIMF / 4));
    int o4 = (int)(idx % (DIMF / 4));

    float4 v[NBR];
    float4 mx = make_float4(-1e30f, -1e30f, -1e30f, -1e30f);
#pragma unroll
    for (int mm = 0; mm < NBR; mm++) {
        const __half2* a2 = (const __half2*)(att + ((size_t)mm * BSZ + b) * DIMF) + o4 * 2;
        float2 lo = __half22float2(a2[0]);
        float2 hi = __half22float2(a2[1]);
        v[mm] = make_float4(lo.x, lo.y, hi.x, hi.y);
        mx.x = fmaxf(mx.x, v[mm].x); mx.y = fmaxf(mx.y, v[mm].y);
        mx.z = fmaxf(mx.z, v[mm].z); mx.w = fmaxf(mx.w, v[mm].w);
    }
    float4 s = make_float4(0.f, 0.f, 0.f, 0.f);
#pragma unroll
    for (int mm = 0; mm < NBR; mm++) {
        v[mm].x = __expf(v[mm].x - mx.x); s.x += v[mm].x;
        v[mm].y = __expf(v[mm].y - mx.y); s.y += v[mm].y;
        v[mm].z = __expf(v[mm].z - mx.z); s.z += v[mm].z;
        v[mm].w = __expf(v[mm].w - mx.w); s.w += v[mm].w;
    }
    s.x = 1.f / s.x; s.y = 1.f / s.y; s.z = 1.f / s.z; s.w = 1.f / s.w;
    float4 acc = make_float4(0.f, 0.f, 0.f, 0.f);
    const float4* xp = (const float4*)(x + (size_t)b * XROW) + o4;
#pragma unroll
    for (int mm = 0; mm < NBR; mm++) {
        float4 xv = xp[mm * (DIMF / 4)];
        acc.x += v[mm].x * s.x * xv.x;
        acc.y += v[mm].y * s.y * xv.y;
        acc.z += v[mm].z * s.z * xv.z;
        acc.w += v[mm].w * s.w * xv.w;
    }
    ((float4*)out)[idx] = acc;
}

// ---------------- fused head tail: l2 (relu+BN) + l3, fp32 exact ----------------
__global__ __launch_bounds__(256) void head23(
    const float* __restrict__ hA,
    const float* __restrict__ l2W, const float* __restrict__ l2b,
    const float* __restrict__ bng, const float* __restrict__ bnb,
    const float* __restrict__ l3W, const float* __restrict__ l3b,
    float* __restrict__ out)
{
    __shared__ float W2[32 * 128];
    __shared__ float W3[20 * 32];
    __shared__ float b2[32], g2[32], be2[32], b3[20];
    const int tid = threadIdx.x;
    for (int i = tid; i < 32 * 128; i += 256) W2[i] = l2W[i];
    for (int i = tid; i < 20 * 32; i += 256) W3[i] = l3W[i];
    if (tid < 32) { b2[tid] = l2b[tid]; g2[tid] = bng[tid]; be2[tid] = bnb[tid]; }
    if (tid < 20) b3[tid] = l3b[tid];
    __syncthreads();

    const int r = blockIdx.x * 256 + tid;   // 4096 rows, grid 16
    const float inv = rsqrtf(1.0f + 1e-5f);

    float acc[32];
#pragma unroll
    for (int j = 0; j < 32; j++) acc[j] = 0.f;
    const float4* hr = (const float4*)(hA + (size_t)r * 128);
#pragma unroll 4
    for (int k4 = 0; k4 < 32; k4++) {
        float4 hv = hr[k4];
#pragma unroll
        for (int j = 0; j < 32; j++) {
            const float* w = W2 + j * 128 + k4 * 4;
            acc[j] += hv.x * w[0] + hv.y * w[1] + hv.z * w[2] + hv.w * w[3];
        }
    }
    float h2[32];
#pragma unroll
    for (int j = 0; j < 32; j++)
        h2[j] = fmaxf(acc[j] + b2[j], 0.f) * g2[j] * inv + be2[j];
#pragma unroll
    for (int cidx = 0; cidx < 20; cidx++) {
        float s = b3[cidx];
#pragma unroll
        for (int j = 0; j < 32; j++) s += h2[j] * W3[cidx * 32 + j];
        out[(size_t)r * 20 + cidx] = s;
    }
}

// ---------------- launch ----------------
extern "C" void kernel_launch(void* const* d_in, const int* in_sizes, int n_in,
                              void* d_out, int out_size) {
    const float* x      = (const float*)d_in[0];
    const float* g      = (const float*)d_in[1];
    const float* fc1_W  = (const float*)d_in[2];
    const float* fc1_b  = (const float*)d_in[3];
    const float* bn1_g  = (const float*)d_in[4];
    const float* bn1_b  = (const float*)d_in[5];
    const float* fc2_W  = (const float*)d_in[6];
    const float* fc2_b  = (const float*)d_in[7];
    const float* fcs_W  = (const float*)d_in[8];
    const float* fcs_b  = (const float*)d_in[9];
    const float* gfcs_W = (const float*)d_in[10];
    const float* gfcs_b = (const float*)d_in[11];
    const float* l1_W   = (const float*)d_in[12];
    const float* l1_b   = (const float*)d_in[13];
    const float* bna_g  = (const float*)d_in[14];
    const float* bna_b  = (const float*)d_in[15];
    const float* l2_W   = (const float*)d_in[16];
    const float* l2_b   = (const float*)d_in[17];
    const float* bnb_g  = (const float*)d_in[18];
    const float* bnb_b  = (const float*)d_in[19];
    const float* l3_W   = (const float*)d_in[20];
    const float* l3_b   = (const float*)d_in[21];
    float* out = (float*)d_out;

    float *fea_u, *h1, *fea_z, *fea_v, *hA, *Wc, *fcsT, *bc;
    __half* att;
    cudaGetSymbolAddress((void**)&fea_u, g_fea_u);
    cudaGetSymbolAddress((void**)&h1,    g_h1);
    cudaGetSymbolAddress((void**)&fea_z, g_fea_z);
    cudaGetSymbolAddress((void**)&att,   g_att);
    cudaGetSymbolAddress((void**)&fea_v, g_fea_v);
    cudaGetSymbolAddress((void**)&hA,    g_hA);
    cudaGetSymbolAddress((void**)&Wc,    g_Wc);
    cudaGetSymbolAddress((void**)&fcsT,  g_fcsT);
    cudaGetSymbolAddress((void**)&bc,    g_bc);

    const int SMEM2  = 2 * (128 + 128) * 36 * 4;   // MI=2: 73728 B
    const int SMEM1  = 2 * (64 + 128) * 36 * 4;    // MI=1: 55296 B
    const int ASMEM  = 4 * AT_STAGE;               // att_cp: 196608 B
    cudaFuncSetAttribute(gemm2<0,1,1>, cudaFuncAttributeMaxDynamicSharedMemorySize, SMEM1);
    cudaFuncSetAttribute(gemm2<1,0,1>, cudaFuncAttributeMaxDynamicSharedMemorySize, SMEM1);
    cudaFuncSetAttribute(gemm2<0,1,2>, cudaFuncAttributeMaxDynamicSharedMemorySize, SMEM2);
    cudaFuncSetAttribute(att_cp,       cudaFuncAttributeMaxDynamicSharedMemorySize, ASMEM);

    // ---- fork a side stream for the weight-prep branch (graph-capture legal) ----
    cudaStream_t s2;
    cudaStreamCreateWithFlags(&s2, cudaStreamNonBlocking);
    cudaEvent_t e0, e1;
    cudaEventCreateWithFlags(&e0, cudaEventDisableTiming);
    cudaEventCreateWithFlags(&e1, cudaEventDisableTiming);

    cudaEventRecord(e0, 0);
    cudaStreamWaitEvent(s2, e0, 0);

    // --- branch S2: weight prep (setup_misc -> Wc fold) ---
    setup_misc<<<dim3(12, 13, NBR), dim3(32, 8), 0, s2>>>(fcs_W, fcsT, gfcs_W, gfcs_b, fcs_b, bc);
    gemm2<0,1,2><<<dim3(3, 6, NBR), 256, SMEM2, s2>>>(
        gfcs_W, (long)DIMF * GW, GW, DD,  nullptr, 0, 0, 0,
        fcsT, (long)DD * DD, DD,  nullptr, 0, 0,
        nullptr, 0, nullptr, nullptr,
        Wc, (long)DIMF * DD, DD);
    cudaEventRecord(e1, s2);

    // --- main stream: activation chain ---
    reduce_x<<<(BSZ * DIMF / 4 + 255) / 256, 256>>>(x, fea_u);

    gemm2<1,0,1><<<dim3(3, 64, 1), 256, SMEM1>>>(
        fea_u, 0, DIMF, DIMF,  nullptr, 0, 0, 0,
        fc1_W, 0, DIMF,  nullptr, 0, 0,
        fc1_b, 0, bn1_g, bn1_b, h1, 0, DD);

    gemm2<0,1,1><<<dim3(3, 64, 1), 256, SMEM1>>>(
        h1, 0, DD, DD,  nullptr, 0, 0, 0,
        fc2_W, 0, DD,  nullptr, 0, 0,
        fc2_b, 0, nullptr, nullptr, fea_z, 0, DD);

    // join: att needs Wc/bc from s2
    cudaStreamWaitEvent(0, e1, 0);

    // att (single fused-K tensor GEMM; fp16 logit output)
    att_cp<<<dim3(6, 16, NBR), 512, ASMEM>>>(fea_z, g, Wc, gfcs_W + DD, GW, bc, att);

    // softmax over m + weighted sum with x
    softmax_wsum<<<(BSZ * DIMF / 4 + 255) / 256, 256>>>(att, x, fea_v);

    // classifier head: l1 via tensor GEMM, l2+l3 fused scalar kernel
    gemm2<1,0,1><<<dim3(1, 64, 1), 256, SMEM1>>>(
        fea_v, 0, DIMF, DIMF,  nullptr, 0, 0, 0,
        l1_W, 0, DIMF,  nullptr, 0, 0,
        l1_b, 0, bna_g, bna_b, hA, 0, 128);

    head23<<<16, 256>>>(hA, l2_W, l2_b, bnb_g, bnb_b, l3_W, l3_b, out);

    cudaEventDestroy(e0);
    cudaEventDestroy(e1);
    cudaStreamDestroy(s2);
}

// round 15
// speedup vs baseline: 1.5104x; 1.3344x over previous
#include <cuda_runtime.h>
#include <cuda_fp16.h>
#include <cstdint>

#define NBR   19
#define DIMF  768
#define DD    384
#define BSZ   4096
#define XROW  (NBR * DIMF)   // 14592
#define GW    (DIMF + DD)    // 1152

// ---------------- scratch (device globals) ----------------
__device__ float  g_fea_u[(size_t)BSZ * DIMF];
__device__ float  g_h1[(size_t)BSZ * DD];
__device__ __half g_fea_z[(size_t)BSZ * DD];            // fp16 fea_z
__device__ __half g_att[(size_t)NBR * BSZ * DIMF];      // fp16 logits
__device__ float  g_fea_v[(size_t)BSZ * DIMF];
__device__ float  g_hA[(size_t)BSZ * 128];
__device__ __half g_Wch[(size_t)NBR * DIMF * DD];       // fp16 folded weights
__device__ float  g_fcsT[(size_t)NBR * DD * DD];
__device__ float  g_bc[(size_t)NBR * DIMF];
__device__ __half g_gh[(size_t)BSZ * XROW];             // fp16 g
__device__ __half g_WBh[(size_t)NBR * DIMF * DIMF];     // fp16 gfcsB

// ---------------- helpers ----------------
__device__ __forceinline__ uint32_t f2tf32(float x) {
    uint32_t u;
    asm("cvt.rna.tf32.f32 %0, %1;" : "=r"(u) : "f"(x));
    return u;
}
__device__ __forceinline__ float rnd1(float x) { return __uint_as_float(f2tf32(x)); }
__device__ __forceinline__ float4 rnd4(float4 v) {
    v.x = rnd1(v.x); v.y = rnd1(v.y); v.z = rnd1(v.z); v.w = rnd1(v.w);
    return v;
}
__device__ __forceinline__ uint32_t h2u(__half2 h) {
    return *reinterpret_cast<uint32_t*>(&h);
}
__device__ __forceinline__ void ldsm4(uint32_t a, uint32_t r[4]) {
    asm volatile("ldmatrix.sync.aligned.m8n8.x4.shared.b16 {%0,%1,%2,%3}, [%4];"
                 : "=r"(r[0]), "=r"(r[1]), "=r"(r[2]), "=r"(r[3]) : "r"(a));
}
__device__ __forceinline__ void cpa16(uint32_t dst, const void* src) {
    asm volatile("cp.async.cg.shared.global [%0], [%1], 16;" :: "r"(dst), "l"(src));
}

// =====================================================================
// att_h: att[m][b][o] = sum_k A[b][k]*B[o][k] + bc[m][o]   (fp16 MMA)
//   A = [fea_z_h (384) | g_h[:,m,:] (768)]   fp16
//   B = [Wc_h[m] (384) | WB_h[m] (768)]      fp16
// Tile 256x128, k-chunk 64 fp16 (128B rows), 512 threads (warps 4x4,
// warp tile 64x32), mma m16n8k16.f16, 4-stage cp.async pipeline,
// XOR-swizzled smem, ldmatrix feeds (same addressing as tf32 version:
// one 16B chunk = k8 fp16 per matrix column pair). Output fp16 logits.
// =====================================================================
#define AT_STAGE 49152          // 32768 (A) + 16384 (B) bytes per stage
__global__ __launch_bounds__(512) void att_h(
    const __half* __restrict__ fea_z,
    const __half* __restrict__ gh,
    const __half* __restrict__ Wc,
    const __half* __restrict__ WBh,
    const float* __restrict__ bc,
    __half* __restrict__ att)
{
    extern __shared__ char smraw[];
    const uint32_t sbase = (uint32_t)__cvta_generic_to_shared(smraw);
    const int tid = threadIdx.x;
    const int m  = blockIdx.z;
    const int bm = blockIdx.y * 256;
    const int bn = blockIdx.x * 128;

    const __half* A1 = gh + (size_t)m * DIMF;
    const __half* B0 = Wc + (size_t)m * DIMF * DD;
    const __half* B1 = WBh + (size_t)m * DIMF * DIMF;

    const int arow = tid >> 3;          // A rows at +0,+64,+128,+192
    const int ach  = tid & 7;           // 16B chunk (8 fp16) within 128B row
    const int KT = GW / 64;             // 18 chunks of k=64

    auto issue = [&](int kt) {
        const int s = kt & 3;
        const uint32_t Ab = sbase + s * AT_STAGE;
        const uint32_t Bb = Ab + 32768;
        const int kb = kt * 64;
        const bool seg0 = kb < DD;
        const int ca = (seg0 ? kb : kb - DD) + ach * 8;   // element offset
#pragma unroll
        for (int i = 0; i < 4; i++) {
            const int row = arow + i * 64;
            const __half* src = seg0 ? (fea_z + (size_t)(bm + row) * DD + ca)
                                     : (A1 + (size_t)(bm + row) * XROW + ca);
            cpa16(Ab + row * 128 + ((ach ^ (row & 7)) * 16), src);
        }
#pragma unroll
        for (int i = 0; i < 2; i++) {
            const int row = (tid >> 3) + i * 64;   // 0..127
            const __half* src = seg0 ? (B0 + (size_t)(bn + row) * DD + ca)
                                     : (B1 + (size_t)(bn + row) * DIMF + ca);
            cpa16(Bb + row * 128 + ((ach ^ (row & 7)) * 16), src);
        }
        asm volatile("cp.async.commit_group;" ::: "memory");
    };

    const int warp = tid >> 5, lane = tid & 31;
    const int wm = warp & 3, wn = warp >> 2;
    const int lr = lane >> 2, lc = lane & 3;

    const int l7 = lane & 7;
    const int a_row_base = wm * 64 + ((lane >> 3) & 1) * 8 + l7;
    const int b_row_base = wn * 32 + (lane >> 4) * 8 + l7;
    const int a_chsel = (lane >> 4);
    const int b_chsel = ((lane >> 3) & 1);

    float c[4][4][4];
#pragma unroll
    for (int a = 0; a < 4; a++)
#pragma unroll
        for (int b = 0; b < 4; b++)
#pragma unroll
            for (int d = 0; d < 4; d++) c[a][b][d] = 0.f;

    issue(0);
    issue(1);
    issue(2);

    for (int kt = 0; kt < KT; kt++) {
        if (kt + 2 <= KT - 1)
            asm volatile("cp.async.wait_group 2;" ::: "memory");
        else if (kt + 1 <= KT - 1)
            asm volatile("cp.async.wait_group 1;" ::: "memory");
        else
            asm volatile("cp.async.wait_group 0;" ::: "memory");
        __syncthreads();

        if (kt + 3 < KT) issue(kt + 3);

        const int s = kt & 3;
        const uint32_t Ab = sbase + s * AT_STAGE;
        const uint32_t Bb = Ab + 32768;
#pragma unroll
        for (int ks = 0; ks < 4; ks++) {    // 4 k16 steps per k64 chunk
            uint32_t af[4][4];
#pragma unroll
            for (int mi = 0; mi < 4; mi++) {
                const int row = a_row_base + mi * 16;
                ldsm4(Ab + row * 128 + (((ks * 2 + a_chsel) ^ l7) * 16), af[mi]);
            }
            uint32_t bf[2][4];
#pragma unroll
            for (int np = 0; np < 2; np++) {
                const int row = b_row_base + np * 16;
                ldsm4(Bb + row * 128 + (((ks * 2 + b_chsel) ^ l7) * 16), bf[np]);
            }
#pragma unroll
            for (int np = 0; np < 2; np++)
#pragma unroll
                for (int sb = 0; sb < 2; sb++) {
                    const int ni = np * 2 + sb;
#pragma unroll
                    for (int mi = 0; mi < 4; mi++)
                        asm volatile(
                            "mma.sync.aligned.m16n8k16.row.col.f32.f16.f16.f32 "
                            "{%0,%1,%2,%3},{%4,%5,%6,%7},{%8,%9},{%0,%1,%2,%3};\n"
                            : "+f"(c[mi][ni][0]), "+f"(c[mi][ni][1]),
                              "+f"(c[mi][ni][2]), "+f"(c[mi][ni][3])
                            : "r"(af[mi][0]), "r"(af[mi][1]),
                              "r"(af[mi][2]), "r"(af[mi][3]),
                              "r"(bf[np][2 * sb]), "r"(bf[np][2 * sb + 1]));
                }
        }
    }

    // epilogue: bias + fp16 store
    float bl[4][2];
#pragma unroll
    for (int ni = 0; ni < 4; ni++) {
        const int col = bn + wn * 32 + ni * 8 + 2 * lc;
        bl[ni][0] = bc[(size_t)m * DIMF + col];
        bl[ni][1] = bc[(size_t)m * DIMF + col + 1];
    }
    __half* Cm = att + (size_t)m * BSZ * DIMF;
#pragma unroll
    for (int mi = 0; mi < 4; mi++) {
        const int row = bm + wm * 64 + mi * 16 + lr;
#pragma unroll
        for (int ni = 0; ni < 4; ni++) {
            const int col = bn + wn * 32 + ni * 8 + 2 * lc;
            __half2 v0 = __floats2half2_rn(c[mi][ni][0] + bl[ni][0], c[mi][ni][1] + bl[ni][1]);
            __half2 v1 = __floats2half2_rn(c[mi][ni][2] + bl[ni][0], c[mi][ni][3] + bl[ni][1]);
            *(__half2*)(Cm + (size_t)row * DIMF + col) = v0;
            *(__half2*)(Cm + (size_t)(row + 8) * DIMF + col) = v1;
        }
    }
}

// ---------------- generic tf32 NT GEMM (mma.sync + ldmatrix) ----------------
// OUTH=1: write __half output (C cast to __half*)
template<int MODE, int OUTH, int MI>
__global__ __launch_bounds__(256, 2) void gemm2(
    const float* __restrict__ A0, long sA0z, int lda0, int K0,
    const float* __restrict__ A1, long sA1z, int lda1, int K1,
    const float* __restrict__ B0, long sB0z, int ldb0,
    const float* __restrict__ B1, long sB1z, int ldb1,
    const float* __restrict__ bias, long sBiasZ,
    const float* __restrict__ bng, const float* __restrict__ bnb,
    float* __restrict__ C, long sCz, int N)
{
    const int K  = K0 + K1;
    const int KT = K >> 5;
    constexpr int MROWS = MI * 64;

    extern __shared__ float sm[];
    float* As  = sm;
    float* Bsm = sm + 2 * MROWS * 36;

    const int tid = threadIdx.x;
    const int z   = blockIdx.z;
    A0 += z * sA0z;
    if (A1) A1 += z * sA1z;
    B0 += z * sB0z;
    if (B1) B1 += z * sB1z;
    if (bias) bias += z * sBiasZ;

    const int bm = blockIdx.y * MROWS;
    const int bn = blockIdx.x * 128;

    const int lrow = tid >> 3;
    const int c4   = (tid & 7) * 4;

    float4 a_stg[2 * MI], b_stg[4];

    auto ldTiles = [&](int kt) {
        const int gk = kt * 32 + c4;
#pragma unroll
        for (int i = 0; i < 2 * MI; i++) {
            const int row = lrow + i * 32;
            const float* s = (gk < K0) ? (A0 + (long)(bm + row) * lda0 + gk)
                                       : (A1 + (long)(bm + row) * lda1 + (gk - K0));
            a_stg[i] = *(const float4*)s;
        }
#pragma unroll
        for (int i = 0; i < 4; i++) {
            const int row = lrow + i * 32;
            int j = bn + row; if (j > N - 1) j = N - 1;
            const float* s = (gk < K0) ? (B0 + (long)j * ldb0 + gk)
                                       : (B1 + (long)j * ldb1 + (gk - K0));
            b_stg[i] = *(const float4*)s;
        }
    };
    auto stTiles = [&](int buf) {
        float* a = As  + buf * MROWS * 36;
        float* b = Bsm + buf * 128 * 36;
#pragma unroll
        for (int i = 0; i < 2 * MI; i++)
            *(float4*)(a + (lrow + i * 32) * 36 + c4) = rnd4(a_stg[i]);
#pragma unroll
        for (int i = 0; i < 4; i++)
            *(float4*)(b + (lrow + i * 32) * 36 + c4) = rnd4(b_stg[i]);
    };

    float c[MI][8][4];
#pragma unroll
    for (int a = 0; a < MI; a++)
#pragma unroll
        for (int b2 = 0; b2 < 8; b2++)
#pragma unroll
            for (int d = 0; d < 4; d++) c[a][b2][d] = 0.f;

    const int warp = tid >> 5, lane = tid & 31;
    const int wm = warp & 3, wn = warp >> 2;
    const int lr = lane >> 2, lc = lane & 3;

    const int a_row = wm * (MI * 16) + ((lane >> 3) & 1) * 8 + (lane & 7);
    const int a_col = (lane >> 4) * 4;
    const uint32_t aoff = (uint32_t)((a_row * 36 + a_col) * 4);
    const int b_row = wn * 64 + (lane >> 4) * 8 + (lane & 7);
    const int b_col = ((lane >> 3) & 1) * 4;
    const uint32_t boff = (uint32_t)((b_row * 36 + b_col) * 4);

    const uint32_t sA = (uint32_t)__cvta_generic_to_shared(As);
    const uint32_t sB = (uint32_t)__cvta_generic_to_shared(Bsm);
    const uint32_t ABUF = MROWS * 36 * 4;
    const uint32_t BBUF = 128 * 36 * 4;

    ldTiles(0);
    stTiles(0);
    __syncthreads();

    for (int kt = 0; kt < KT; kt++) {
        const bool has_next = (kt + 1 < KT);
        if (has_next) ldTiles(kt + 1);

        const uint32_t aBuf = sA + (kt & 1) * ABUF + aoff;
        const uint32_t bBuf = sB + (kt & 1) * BBUF + boff;
#pragma unroll
        for (int ks = 0; ks < 4; ks++) {
            const uint32_t kByte = (uint32_t)(ks * 8 * 4);
            uint32_t af[MI][4];
#pragma unroll
            for (int mi = 0; mi < MI; mi++)
                ldsm4(aBuf + mi * (16 * 36 * 4) + kByte, af[mi]);
            uint32_t bf[4][4];
#pragma unroll
            for (int np = 0; np < 4; np++)
                ldsm4(bBuf + np * (16 * 36 * 4) + kByte, bf[np]);
#pragma unroll
            for (int np = 0; np < 4; np++)
#pragma unroll
                for (int s = 0; s < 2; s++) {
                    const int ni = np * 2 + s;
#pragma unroll
                    for (int mi = 0; mi < MI; mi++)
                        asm volatile(
                            "mma.sync.aligned.m16n8k8.row.col.f32.tf32.tf32.f32 "
                            "{%0,%1,%2,%3},{%4,%5,%6,%7},{%8,%9},{%0,%1,%2,%3};\n"
                            : "+f"(c[mi][ni][0]), "+f"(c[mi][ni][1]),
                              "+f"(c[mi][ni][2]), "+f"(c[mi][ni][3])
                            : "r"(af[mi][0]), "r"(af[mi][1]),
                              "r"(af[mi][2]), "r"(af[mi][3]),
                              "r"(bf[np][2 * s]), "r"(bf[np][2 * s + 1]));
                }
        }
        if (has_next) stTiles((kt + 1) & 1);
        __syncthreads();
    }

    const float inv = rsqrtf(1.0f + 1e-5f);
#pragma unroll
    for (int mi = 0; mi < MI; mi++) {
        const int row = bm + wm * (MI * 16) + mi * 16 + lr;
#pragma unroll
        for (int ni = 0; ni < 8; ni++) {
            const int col = bn + wn * 64 + ni * 8 + 2 * lc;
#pragma unroll
            for (int h = 0; h < 2; h++) {
                const int r = row + h * 8;
#pragma unroll
                for (int q = 0; q < 2; q++) {
                    const int j = col + q;
                    if (j < N) {
                        float v = c[mi][ni][h * 2 + q];
                        if (bias) v += bias[j];
                        if (MODE == 1) v = fmaxf(v, 0.f) * bng[j] * inv + bnb[j];
                        if (OUTH)
                            ((__half*)C)[z * sCz + (long)r * N + j] = __float2half_rn(v);
                        else
                            C[z * sCz + (long)r * N + j] = v;
                    }
                }
            }
        }
    }
}

// ---------------- fea_u = sum over the 19 branches of x (float4) ----------------
__global__ void reduce_x(const float* __restrict__ x, float* __restrict__ out) {
    long idx = (long)blockIdx.x * blockDim.x + threadIdx.x;
    if (idx >= (long)BSZ * DIMF / 4) return;
    int b  = (int)(idx / (DIMF / 4));
    int d4 = (int)(idx % (DIMF / 4));
    const float4* p = (const float4*)(x + (size_t)b * XROW) + d4;
    float4 s = make_float4(0.f, 0.f, 0.f, 0.f);
#pragma unroll
    for (int mm = 0; mm < NBR; mm++) {
        float4 v = p[mm * (DIMF / 4)];
        s.x += v.x; s.y += v.y; s.z += v.z; s.w += v.w;
    }
    ((float4*)out)[idx] = s;
}

// ---------------- convert g -> fp16 (8 elems/thread) ----------------
__global__ void conv_g(const float* __restrict__ g, __half* __restrict__ gh) {
    long i = (long)blockIdx.x * blockDim.x + threadIdx.x;   // 8-elem index
    if (i >= (long)BSZ * XROW / 8) return;
    const float4* s = (const float4*)g + i * 2;
    float4 a = s[0], b = s[1];
    uint4 o;
    o.x = h2u(__floats2half2_rn(a.x, a.y));
    o.y = h2u(__floats2half2_rn(a.z, a.w));
    o.z = h2u(__floats2half2_rn(b.x, b.y));
    o.w = h2u(__floats2half2_rn(b.z, b.w));
    ((uint4*)gh)[i] = o;
}

// ---------------- convert gfcsB slice -> fp16 dense ----------------
__global__ void conv_wb(const float* __restrict__ gfcsW, __half* __restrict__ wbh) {
    long i = (long)blockIdx.x * blockDim.x + threadIdx.x;   // 8-elem index
    if (i >= (long)NBR * DIMF * DIMF / 8) return;
    long c8  = i % (DIMF / 8);
    long row = i / (DIMF / 8);          // m*768 + o
    const float4* s = (const float4*)(gfcsW + row * GW + DD + c8 * 8);
    float4 a = s[0], b = s[1];
    uint4 o;
    o.x = h2u(__floats2half2_rn(a.x, a.y));
    o.y = h2u(__floats2half2_rn(a.z, a.w));
    o.z = h2u(__floats2half2_rn(b.x, b.y));
    o.w = h2u(__floats2half2_rn(b.z, b.w));
    ((uint4*)wbh)[i] = o;
}

// ---------------- setup: transpose fcs_W  +  folded bias (merged) ----------------
__global__ void setup_misc(const float* __restrict__ fcsW, float* __restrict__ fcsT,
                           const float* __restrict__ gfcsW, const float* __restrict__ gfcsB,
                           const float* __restrict__ fcsB, float* __restrict__ bc)
{
    const int m = blockIdx.z;
    if (blockIdx.y < 12) {
        __shared__ float t[32][33];
        const int i0 = blockIdx.y * 32, d0 = blockIdx.x * 32;
        const float* src = fcsW + (size_t)m * DD * DD;
        float* dst       = fcsT + (size_t)m * DD * DD;
        const int x = threadIdx.x, y = threadIdx.y;
#pragma unroll
        for (int yy = y; yy < 32; yy += 8)
            t[yy][x] = src[(size_t)(i0 + yy) * DD + d0 + x];
        __syncthreads();
#pragma unroll
        for (int yy = y; yy < 32; yy += 8)
            dst[(size_t)(d0 + yy) * DD + i0 + x] = t[x][yy];
    } else {
        const int tid = threadIdx.y * 32 + threadIdx.x;
        const int w = tid >> 5, lane = tid & 31;
        const float* fb = fcsB + m * DD;
        for (int j = 0; j < 8; j++) {
            const int o = blockIdx.x * 64 + w * 8 + j;
            const float* wp = gfcsW + ((size_t)m * DIMF + o) * GW;
            float s = 0.f;
            for (int i = lane; i < DD; i += 32) s += wp[i] * fb[i];
#pragma unroll
            for (int off = 16; off; off >>= 1) s += __shfl_xor_sync(0xffffffffu, s, off);
            if (lane == 0) bc[(size_t)m * DIMF + o] = s + gfcsB[(size_t)m * DIMF + o];
        }
    }
}

// ---------------- softmax over m (fp16 logits) + weighted sum with x ----------------
__global__ void softmax_wsum(const __half* __restrict__ att,
                             const float* __restrict__ x,
                             float* __restrict__ out) {
    long idx = (long)blockIdx.x * blockDim.x + threadIdx.x;
    if (idx >= (long)BSZ * DIMF / 4) return;
    int b  = (int)(idx / (DIMF / 4));
    int o4 = (int)(idx % (DIMF / 4));

    float4 v[NBR];
    float4 mx = make_float4(-1e30f, -1e30f, -1e30f, -1e30f);
#pragma unroll
    for (int mm = 0; mm < NBR; mm++) {
        const __half2* a2 = (const __half2*)(att + ((size_t)mm * BSZ + b) * DIMF) + o4 * 2;
        float2 lo = __half22float2(a2[0]);
        float2 hi = __half22float2(a2[1]);
        v[mm] = make_float4(lo.x, lo.y, hi.x, hi.y);
        mx.x = fmaxf(mx.x, v[mm].x); mx.y = fmaxf(mx.y, v[mm].y);
        mx.z = fmaxf(mx.z, v[mm].z); mx.w = fmaxf(mx.w, v[mm].w);
    }
    float4 s = make_float4(0.f, 0.f, 0.f, 0.f);
#pragma unroll
    for (int mm = 0; mm < NBR; mm++) {
        v[mm].x = __expf(v[mm].x - mx.x); s.x += v[mm].x;
        v[mm].y = __expf(v[mm].y - mx.y); s.y += v[mm].y;
        v[mm].z = __expf(v[mm].z - mx.z); s.z += v[mm].z;
        v[mm].w = __expf(v[mm].w - mx.w); s.w += v[mm].w;
    }
    s.x = 1.f / s.x; s.y = 1.f / s.y; s.z = 1.f / s.z; s.w = 1.f / s.w;
    float4 acc = make_float4(0.f, 0.f, 0.f, 0.f);
    const float4* xp = (const float4*)(x + (size_t)b * XROW) + o4;
#pragma unroll
    for (int mm = 0; mm < NBR; mm++) {
        float4 xv = xp[mm * (DIMF / 4)];
        acc.x += v[mm].x * s.x * xv.x;
        acc.y += v[mm].y * s.y * xv.y;
        acc.z += v[mm].z * s.z * xv.z;
        acc.w += v[mm].w * s.w * xv.w;
    }
    ((float4*)out)[idx] = acc;
}

// ---------------- fused head tail: l2 (relu+BN) + l3, fp32 exact ----------------
__global__ __launch_bounds__(256) void head23(
    const float* __restrict__ hA,
    const float* __restrict__ l2W, const float* __restrict__ l2b,
    const float* __restrict__ bng, const float* __restrict__ bnb,
    const float* __restrict__ l3W, const float* __restrict__ l3b,
    float* __restrict__ out)
{
    __shared__ float W2[32 * 128];
    __shared__ float W3[20 * 32];
    __shared__ float b2[32], g2[32], be2[32], b3[20];
    const int tid = threadIdx.x;
    for (int i = tid; i < 32 * 128; i += 256) W2[i] = l2W[i];
    for (int i = tid; i < 20 * 32; i += 256) W3[i] = l3W[i];
    if (tid < 32) { b2[tid] = l2b[tid]; g2[tid] = bng[tid]; be2[tid] = bnb[tid]; }
    if (tid < 20) b3[tid] = l3b[tid];
    __syncthreads();

    const int r = blockIdx.x * 256 + tid;
    const float inv = rsqrtf(1.0f + 1e-5f);

    float acc[32];
#pragma unroll
    for (int j = 0; j < 32; j++) acc[j] = 0.f;
    const float4* hr = (const float4*)(hA + (size_t)r * 128);
#pragma unroll 4
    for (int k4 = 0; k4 < 32; k4++) {
        float4 hv = hr[k4];
#pragma unroll
        for (int j = 0; j < 32; j++) {
            const float* w = W2 + j * 128 + k4 * 4;
            acc[j] += hv.x * w[0] + hv.y * w[1] + hv.z * w[2] + hv.w * w[3];
        }
    }
    float h2[32];
#pragma unroll
    for (int j = 0; j < 32; j++)
        h2[j] = fmaxf(acc[j] + b2[j], 0.f) * g2[j] * inv + be2[j];
#pragma unroll
    for (int cidx = 0; cidx < 20; cidx++) {
        float s = b3[cidx];
#pragma unroll
        for (int j = 0; j < 32; j++) s += h2[j] * W3[cidx * 32 + j];
        out[(size_t)r * 20 + cidx] = s;
    }
}

// ---------------- launch ----------------
extern "C" void kernel_launch(void* const* d_in, const int* in_sizes, int n_in,
                              void* d_out, int out_size) {
    const float* x      = (const float*)d_in[0];
    const float* g      = (const float*)d_in[1];
    const float* fc1_W  = (const float*)d_in[2];
    const float* fc1_b  = (const float*)d_in[3];
    const float* bn1_g  = (const float*)d_in[4];
    const float* bn1_b  = (const float*)d_in[5];
    const float* fc2_W  = (const float*)d_in[6];
    const float* fc2_b  = (const float*)d_in[7];
    const float* fcs_W  = (const float*)d_in[8];
    const float* fcs_b  = (const float*)d_in[9];
    const float* gfcs_W = (const float*)d_in[10];
    const float* gfcs_b = (const float*)d_in[11];
    const float* l1_W   = (const float*)d_in[12];
    const float* l1_b   = (const float*)d_in[13];
    const float* bna_g  = (const float*)d_in[14];
    const float* bna_b  = (const float*)d_in[15];
    const float* l2_W   = (const float*)d_in[16];
    const float* l2_b   = (const float*)d_in[17];
    const float* bnb_g  = (const float*)d_in[18];
    const float* bnb_b  = (const float*)d_in[19];
    const float* l3_W   = (const float*)d_in[20];
    const float* l3_b   = (const float*)d_in[21];
    float* out = (float*)d_out;

    float *fea_u, *h1, *fea_v, *hA, *fcsT, *bc;
    __half *att, *fea_zh, *Wch, *gh, *WBh;
    cudaGetSymbolAddress((void**)&fea_u,  g_fea_u);
    cudaGetSymbolAddress((void**)&h1,     g_h1);
    cudaGetSymbolAddress((void**)&fea_zh, g_fea_z);
    cudaGetSymbolAddress((void**)&att,    g_att);
    cudaGetSymbolAddress((void**)&fea_v,  g_fea_v);
    cudaGetSymbolAddress((void**)&hA,     g_hA);
    cudaGetSymbolAddress((void**)&Wch,    g_Wch);
    cudaGetSymbolAddress((void**)&fcsT,   g_fcsT);
    cudaGetSymbolAddress((void**)&bc,     g_bc);
    cudaGetSymbolAddress((void**)&gh,     g_gh);
    cudaGetSymbolAddress((void**)&WBh,    g_WBh);

    const int SMEM2  = 2 * (128 + 128) * 36 * 4;
    const int SMEM1  = 2 * (64 + 128) * 36 * 4;
    const int ASMEM  = 4 * AT_STAGE;
    cudaFuncSetAttribute(gemm2<0,1,1>, cudaFuncAttributeMaxDynamicSharedMemorySize, SMEM1);
    cudaFuncSetAttribute(gemm2<1,0,1>, cudaFuncAttributeMaxDynamicSharedMemorySize, SMEM1);
    cudaFuncSetAttribute(gemm2<0,1,2>, cudaFuncAttributeMaxDynamicSharedMemorySize, SMEM2);
    cudaFuncSetAttribute(att_h,        cudaFuncAttributeMaxDynamicSharedMemorySize, ASMEM);

    // ---- fork side streams (graph-capture legal) ----
    cudaStream_t s2, s3;
    cudaStreamCreateWithFlags(&s2, cudaStreamNonBlocking);
    cudaStreamCreateWithFlags(&s3, cudaStreamNonBlocking);
    cudaEvent_t e0, e1, e2;
    cudaEventCreateWithFlags(&e0, cudaEventDisableTiming);
    cudaEventCreateWithFlags(&e1, cudaEventDisableTiming);
    cudaEventCreateWithFlags(&e2, cudaEventDisableTiming);

    cudaEventRecord(e0, 0);
    cudaStreamWaitEvent(s2, e0, 0);
    cudaStreamWaitEvent(s3, e0, 0);

    // --- branch S3: g -> fp16 (no deps; overlaps the activation chain) ---
    conv_g<<<(int)(((long)BSZ * XROW / 8 + 255) / 256), 256, 0, s3>>>(g, gh);
    cudaEventRecord(e2, s3);

    // --- branch S2: weight prep (setup_misc, gfcsB->fp16, Wc fold -> fp16) ---
    setup_misc<<<dim3(12, 13, NBR), dim3(32, 8), 0, s2>>>(fcs_W, fcsT, gfcs_W, gfcs_b, fcs_b, bc);
    conv_wb<<<(int)(((long)NBR * DIMF * DIMF / 8 + 255) / 256), 256, 0, s2>>>(gfcs_W, WBh);
    gemm2<0,1,2><<<dim3(3, 6, NBR), 256, SMEM2, s2>>>(
        gfcs_W, (long)DIMF * GW, GW, DD,  nullptr, 0, 0, 0,
        fcsT, (long)DD * DD, DD,  nullptr, 0, 0,
        nullptr, 0, nullptr, nullptr,
        (float*)Wch, (long)DIMF * DD, DD);
    cudaEventRecord(e1, s2);

    // --- main stream: activation chain ---
    reduce_x<<<(BSZ * DIMF / 4 + 255) / 256, 256>>>(x, fea_u);

    gemm2<1,0,1><<<dim3(3, 64, 1), 256, SMEM1>>>(
        fea_u, 0, DIMF, DIMF,  nullptr, 0, 0, 0,
        fc1_W, 0, DIMF,  nullptr, 0, 0,
        fc1_b, 0, bn1_g, bn1_b, h1, 0, DD);

    gemm2<0,1,1><<<dim3(3, 64, 1), 256, SMEM1>>>(
        h1, 0, DD, DD,  nullptr, 0, 0, 0,
        fc2_W, 0, DD,  nullptr, 0, 0,
        fc2_b, 0, nullptr, nullptr, (float*)fea_zh, 0, DD);

    // joins: att needs Wch/WBh/bc (s2) and gh (s3)
    cudaStreamWaitEvent(0, e1, 0);
    cudaStreamWaitEvent(0, e2, 0);

    // att (fp16 MMA; 2x tensor rate)
    att_h<<<dim3(6, 16, NBR), 512, ASMEM>>>(fea_zh, gh, Wch, WBh, bc, att);

    // softmax over m + weighted sum with x
    softmax_wsum<<<(BSZ * DIMF / 4 + 255) / 256, 256>>>(att, x, fea_v);

    // classifier head: l1 via tensor GEMM, l2+l3 fused scalar kernel
    gemm2<1,0,1><<<dim3(1, 64, 1), 256, SMEM1>>>(
        fea_v, 0, DIMF, DIMF,  nullptr, 0, 0, 0,
        l1_W, 0, DIMF,  nullptr, 0, 0,
        l1_b, 0, bna_g, bna_b, hA, 0, 128);

    head23<<<16, 256>>>(hA, l2_W, l2_b, bnb_g, bnb_b, l3_W, l3_b, out);

    cudaEventDestroy(e0);
    cudaEventDestroy(e1);
    cudaEventDestroy(e2);
    cudaStreamDestroy(s2);
    cudaStreamDestroy(s3);
}